// round 13
// baseline (speedup 1.0000x reference)
#include <cuda_runtime.h>
#include <math.h>
#include <stdint.h>

#define BATCH 8
#define QN 2048
#define KN 2048
#define DIN 1024
#define DPROJ 1024

// ---------------------------------------------------------------------------
// Scratch (__device__ globals; allocation-free).
// Fragment buffers hold tf32 bit patterns in mma-fragment-native order:
//   A-frag tile (16m x 8k) = 128 u32: lane L's uint4 = {A[m+ (L>>2)][k+(L&3)],
//     A[m+8+(L>>2)][k+(L&3)], A[m+(L>>2)][k+4+(L&3)], A[m+8+(L>>2)][k+4+(L&3)]}
//   B-frag tile (16n x 8k) = 128 u32: lane L's uint4 = {B[n+(L>>2)][k+(L&3)],
//     B[n+(L>>2)][k+4+(L&3)], B[n+8+(L>>2)][k+(L&3)], B[n+8+(L>>2)][k+4+(L&3)]}
// (identical per-lane contents to what ldmatrix produced in the validated
//  round-8/9 kernel)
// ---------------------------------------------------------------------------
__device__ uint4 g_qA [(size_t)16384 * 1024 / 4];   // query  -> A-frag (rounded)
__device__ uint4 g_kA [(size_t)16384 * 1024 / 4];   // key    -> A-frag
__device__ uint4 g_vB [(size_t)16384 * 1024 / 4];   // value  -> B-frag
__device__ uint4 g_wqB[(size_t)1024 * 1024 / 4];    // Wq -> B-frag
__device__ uint4 g_wkB[(size_t)1024 * 1024 / 4];    // Wk -> B-frag
__device__ uint4 g_wvA[(size_t)1024 * 1024 / 4];    // Wv -> A-frag
__device__ float g_pq [(size_t)BATCH * QN * DPROJ]; // canonical intermediates
__device__ float g_pk [(size_t)BATCH * KN * DPROJ];
__device__ float g_pvT[(size_t)BATCH * DPROJ * KN];
__device__ uint4 g_pqA[(size_t)16384 * 1024 / 4];   // pq  -> A-frag
__device__ uint4 g_pkB[(size_t)16384 * 1024 / 4];   // pk  -> B-frag
__device__ uint4 g_pvB[(size_t)8192 * 2048 / 4];    // pvT -> B-frag
__device__ uint4 g_atA[(size_t)16384 * 2048 / 4];   // attn -> A-frag

// ---------------------------------------------------------------------------
__device__ __forceinline__ uint32_t f2tf32(float f) {
    uint32_t u;
    asm("cvt.rna.tf32.f32 %0, %1;" : "=r"(u) : "f"(f));
    return u;
}

__device__ __forceinline__ void mma_tf32(float* d, const uint32_t* a, const uint32_t* b) {
    asm volatile(
        "mma.sync.aligned.m16n8k8.row.col.f32.tf32.tf32.f32 "
        "{%0,%1,%2,%3}, {%4,%5,%6,%7}, {%8,%9}, {%0,%1,%2,%3};\n"
        : "+f"(d[0]), "+f"(d[1]), "+f"(d[2]), "+f"(d[3])
        : "r"(a[0]), "r"(a[1]), "r"(a[2]), "r"(a[3]),
          "r"(b[0]), "r"(b[1]));
}

// ---------------------------------------------------------------------------
// Repack canonical row-major [R][K] fp32 -> fragment layout, with rna-tf32
// rounding. ISA=1: A-frag, ISA=0: B-frag. K multiple of 8, R multiple of 16.
// ---------------------------------------------------------------------------
template <int ISA>
__global__ __launch_bounds__(256) void repack_k(
    const float4* __restrict__ in, uint32_t* __restrict__ out, long n4, int K)
{
    const int K4 = K >> 2;
    const long KT = K >> 3;
    long i = (long)blockIdx.x * blockDim.x + threadIdx.x;
    const long st = (long)gridDim.x * blockDim.x;
    for (; i < n4; i += st) {
        float4 v = in[i];
        const long row = i / K4;
        const int k4 = (int)(i - row * K4) << 2;         // multiple of 4
        const long tile = (row >> 4) * KT + (k4 >> 3);
        uint32_t* o = out + tile * 128;
        const int base = (int)(row & 7) << 2;            // lane base
        int reg;
        if (ISA) reg = (int)((row & 8) >> 3) + ((k4 & 4) >> 2) * 2;
        else     reg = (int)((row & 8) >> 3) * 2 + ((k4 & 4) >> 2);
        o[(base + 0) * 4 + reg] = f2tf32(v.x);
        o[(base + 1) * 4 + reg] = f2tf32(v.y);
        o[(base + 2) * 4 + reg] = f2tf32(v.z);
        o[(base + 3) * 4 + reg] = f2tf32(v.w);
    }
}

// ---------------------------------------------------------------------------
// Zero-smem NT tensor GEMM on fragment-layout operands.
// C[m,n] = scale * sum_k A[m,k]*B[n,k] (+bias). tf32 in / fp32 acc.
// Block tile 128x128, 4 warps (2x2), warp tile 64x64. Per k8 step each warp
// does 8 coalesced LDG.128 (4 A-tiles, 4 B-n16-tiles) + 32 MMAs. No barriers.
// BIAS: 0 none, 1 col bias[n], 2 row bias[m]. Strides in uint4 / float elems.
// ---------------------------------------------------------------------------
template <int BIAS>
__global__ __launch_bounds__(128) void gemm_frag(
    const uint4* __restrict__ Af, const uint4* __restrict__ Bf,
    const float* __restrict__ bias, float* __restrict__ C,
    int N, int KT, float scale,
    long aStride, long bStride, long cStride)
{
    const int tid  = threadIdx.x;
    const int lane = tid & 31;
    const int wid  = tid >> 5;
    const int lr   = lane >> 2;
    const int lc   = lane & 3;

    Af += blockIdx.z * aStride;
    Bf += blockIdx.z * bStride;
    C  += blockIdx.z * cStride;

    const int bm = blockIdx.y * 128;
    const int bn = blockIdx.x * 128;
    const int mt0 = (bm >> 4) + (wid & 1) * 4;    // 4 m16 tiles per warp
    const int nt0 = (bn >> 4) + (wid >> 1) * 4;   // 4 n16 tiles per warp

    const uint4* aP[4];
    const uint4* bP[4];
#pragma unroll
    for (int i = 0; i < 4; i++) {
        aP[i] = Af + (size_t)(mt0 + i) * KT * 32 + lane;
        bP[i] = Bf + (size_t)(nt0 + i) * KT * 32 + lane;
    }

    float acc[4][8][4];
#pragma unroll
    for (int i = 0; i < 4; i++)
#pragma unroll
        for (int j = 0; j < 8; j++)
#pragma unroll
            for (int q = 0; q < 4; q++) acc[i][j][q] = 0.f;

    uint4 an[4], bnx[4];
#pragma unroll
    for (int i = 0; i < 4; i++) {
        an[i]  = *aP[i]; aP[i] += 32;
        bnx[i] = *bP[i]; bP[i] += 32;
    }

    for (int kt = 0; kt < KT; kt++) {
        uint4 ac[4], bc[4];
#pragma unroll
        for (int i = 0; i < 4; i++) { ac[i] = an[i]; bc[i] = bnx[i]; }
        if (kt + 1 < KT) {
#pragma unroll
            for (int i = 0; i < 4; i++) {
                an[i]  = *aP[i]; aP[i] += 32;
                bnx[i] = *bP[i]; bP[i] += 32;
            }
        }
#pragma unroll
        for (int fm = 0; fm < 4; fm++) {
            const uint32_t af[4] = {ac[fm].x, ac[fm].y, ac[fm].z, ac[fm].w};
#pragma unroll
            for (int fp = 0; fp < 4; fp++) {
                const uint32_t bf0[2] = {bc[fp].x, bc[fp].y};
                const uint32_t bf1[2] = {bc[fp].z, bc[fp].w};
                mma_tf32(acc[fm][2 * fp],     af, bf0);
                mma_tf32(acc[fm][2 * fp + 1], af, bf1);
            }
        }
    }

    // Epilogue (c-frag layout validated in rounds 7-9)
#pragma unroll
    for (int fm = 0; fm < 4; fm++) {
        const int r = bm + (wid & 1) * 64 + fm * 16 + lr;
        float br0 = 0.f, br1 = 0.f;
        if (BIAS == 2) { br0 = bias[r]; br1 = bias[r + 8]; }
#pragma unroll
        for (int fn = 0; fn < 8; fn++) {
            const int c = bn + (wid >> 1) * 64 + fn * 8 + lc * 2;
            float bc0 = 0.f, bc1 = 0.f;
            if (BIAS == 1) { bc0 = bias[c]; bc1 = bias[c + 1]; }
            float2 v0, v1;
            v0.x = acc[fm][fn][0] * scale + bc0 + br0;
            v0.y = acc[fm][fn][1] * scale + bc1 + br0;
            v1.x = acc[fm][fn][2] * scale + bc0 + br1;
            v1.y = acc[fm][fn][3] * scale + bc1 + br1;
            *(float2*)&C[(long)r * N + c] = v0;
            *(float2*)&C[(long)(r + 8) * N + c] = v1;
        }
    }
}

// ---------------------------------------------------------------------------
// Row softmax with mask (canonical in/out, fp32; masked lanes -> exact 0)
// ---------------------------------------------------------------------------
__global__ __launch_bounds__(256) void softmax_mask(
    float* __restrict__ S, const int* __restrict__ mask)
{
    const int row = blockIdx.x;
    const int b = row / QN;
    float* sp = S + (long)row * KN;
    const int* mp = mask + (long)b * KN;

    const int tid = threadIdx.x;
    __shared__ float red[32];

    float vals[8];
    int ms[8];
    float lmax = -INFINITY;
#pragma unroll
    for (int i = 0; i < 8; i++) {
        int k = tid + i * 256;
        vals[i] = sp[k];
        ms[i] = mp[k];
        if (ms[i]) lmax = fmaxf(lmax, vals[i]);
    }
#pragma unroll
    for (int o = 16; o > 0; o >>= 1)
        lmax = fmaxf(lmax, __shfl_xor_sync(0xffffffffu, lmax, o));
    if ((tid & 31) == 0) red[tid >> 5] = lmax;
    __syncthreads();
    float rmax = (tid < 8) ? red[tid] : -INFINITY;
#pragma unroll
    for (int o = 4; o > 0; o >>= 1)
        rmax = fmaxf(rmax, __shfl_xor_sync(0xffffffffu, rmax, o));
    if (tid == 0) red[0] = rmax;
    __syncthreads();
    rmax = red[0];

    float lsum = 0.f;
#pragma unroll
    for (int i = 0; i < 8; i++) {
        vals[i] = ms[i] ? __expf(vals[i] - rmax) : 0.f;
        lsum += vals[i];
    }
#pragma unroll
    for (int o = 16; o > 0; o >>= 1)
        lsum += __shfl_xor_sync(0xffffffffu, lsum, o);
    __syncthreads();
    if ((tid & 31) == 0) red[tid >> 5] = lsum;
    __syncthreads();
    float rsum = (tid < 8) ? red[tid] : 0.f;
#pragma unroll
    for (int o = 4; o > 0; o >>= 1)
        rsum += __shfl_xor_sync(0xffffffffu, rsum, o);
    if (tid == 0) red[0] = rsum;
    __syncthreads();
    rsum = red[0];

    float inv = (rsum > 0.f) ? (1.f / rsum) : 0.f;
#pragma unroll
    for (int i = 0; i < 8; i++) {
        int k = tid + i * 256;
        sp[k] = vals[i] * inv;
    }
}

// ---------------------------------------------------------------------------
// kernel_launch
// Inputs: query, key, value, mask, Wq, bq, Wk, bk, Wv, bv
// Output: [ctx (B*QN*DPROJ) | attn (B*QN*KN)]
// ---------------------------------------------------------------------------
extern "C" void kernel_launch(void* const* d_in, const int* in_sizes, int n_in,
                              void* d_out, int out_size)
{
    const float* query = (const float*)d_in[0];
    const float* key   = (const float*)d_in[1];
    const float* value = (const float*)d_in[2];
    const int*   mask  = (const int*)d_in[3];
    const float* Wq    = (const float*)d_in[4];
    const float* bq    = (const float*)d_in[5];
    const float* Wk    = (const float*)d_in[6];
    const float* bk    = (const float*)d_in[7];
    const float* Wv    = (const float*)d_in[8];
    const float* bv    = (const float*)d_in[9];

    float* ctx  = (float*)d_out;
    float* attn = (float*)d_out + (size_t)BATCH * QN * DPROJ;

    uint4 *qA, *kA, *vB, *wqB, *wkB, *wvA, *pqA, *pkB, *pvB, *atA;
    float *pq, *pk, *pvT;
    cudaGetSymbolAddress((void**)&qA,  g_qA);
    cudaGetSymbolAddress((void**)&kA,  g_kA);
    cudaGetSymbolAddress((void**)&vB,  g_vB);
    cudaGetSymbolAddress((void**)&wqB, g_wqB);
    cudaGetSymbolAddress((void**)&wkB, g_wkB);
    cudaGetSymbolAddress((void**)&wvA, g_wvA);
    cudaGetSymbolAddress((void**)&pq,  g_pq);
    cudaGetSymbolAddress((void**)&pk,  g_pk);
    cudaGetSymbolAddress((void**)&pvT, g_pvT);
    cudaGetSymbolAddress((void**)&pqA, g_pqA);
    cudaGetSymbolAddress((void**)&pkB, g_pkB);
    cudaGetSymbolAddress((void**)&pvB, g_pvB);
    cudaGetSymbolAddress((void**)&atA, g_atA);

    const long n4big = (long)16384 * 1024 / 4;   // q/k/v, pq, pk
    const long n4w   = (long)1024 * 1024 / 4;    // weights
    const long n4pv  = (long)8192 * 2048 / 4;    // pvT
    const long n4at  = (long)16384 * 2048 / 4;   // attn

    // 1) Inputs -> fragment layout (with tf32 rounding)
    repack_k<1><<<2048, 256>>>((const float4*)query, (uint32_t*)qA, n4big, DIN);
    repack_k<1><<<2048, 256>>>((const float4*)key,   (uint32_t*)kA, n4big, DIN);
    repack_k<0><<<2048, 256>>>((const float4*)value, (uint32_t*)vB, n4big, DIN);
    repack_k<0><<<512, 256>>>((const float4*)Wq, (uint32_t*)wqB, n4w, DIN);
    repack_k<0><<<512, 256>>>((const float4*)Wk, (uint32_t*)wkB, n4w, DIN);
    repack_k<1><<<512, 256>>>((const float4*)Wv, (uint32_t*)wvA, n4w, DIN);

    // 2) Projections. pq/pk: [16384,1024] = q @ W^T + b (col-bias)
    {
        dim3 grid(DPROJ / 128, 16384 / 128, 1);
        gemm_frag<1><<<grid, 128>>>(qA, wqB, bq, pq, DPROJ, DIN / 8, 1.f, 0, 0, 0);
        gemm_frag<1><<<grid, 128>>>(kA, wkB, bk, pk, DPROJ, DIN / 8, 1.f, 0, 0, 0);
    }
    // pvT[d,tok] = Wv @ value^T + bv[d] (row-bias), per batch
    {
        dim3 grid(KN / 128, DPROJ / 128, BATCH);
        gemm_frag<2><<<grid, 128>>>(wvA, vB, bv, pvT, KN, DIN / 8, 1.f,
                                    0, (long)KN * DIN / 4, (long)DPROJ * KN);
    }

    // 3) Intermediates -> fragment layout (rounded)
    repack_k<1><<<2048, 256>>>((const float4*)pq,  (uint32_t*)pqA, n4big, DPROJ);
    repack_k<0><<<2048, 256>>>((const float4*)pk,  (uint32_t*)pkB, n4big, DPROJ);
    repack_k<0><<<2048, 256>>>((const float4*)pvT, (uint32_t*)pvB, n4pv, KN);

    // 4) Scores -> attn region (canonical, unrounded output)
    {
        dim3 grid(KN / 128, QN / 128, BATCH);
        gemm_frag<0><<<grid, 128>>>(pqA, pkB, nullptr, attn, KN, DPROJ / 8,
                                    0.03125f,
                                    (long)QN * DPROJ / 4, (long)KN * DPROJ / 4,
                                    (long)QN * KN);
    }

    // 5) Masked softmax in place
    softmax_mask<<<BATCH * QN, 256>>>(attn, mask);

    // 6) attn -> A-frag (rounded), then ctx = attn @ pvT^T
    repack_k<1><<<2048, 256>>>((const float4*)attn, (uint32_t*)atA, n4at, KN);
    {
        dim3 grid(DPROJ / 128, QN / 128, BATCH);
        gemm_frag<0><<<grid, 128>>>(atA, pvB, nullptr, ctx, DPROJ, KN / 8, 1.f,
                                    (long)QN * KN / 4, (long)DPROJ * KN / 4,
                                    (long)QN * DPROJ);
    }
}

// round 15
// speedup vs baseline: 1.5948x; 1.5948x over previous
#include <cuda_runtime.h>
#include <math.h>
#include <stdint.h>

#define BATCH 8
#define QN 2048
#define KN 2048
#define DIN 1024
#define DPROJ 1024

// ---------------------------------------------------------------------------
// Scratch (__device__ globals; allocation-free).
// All GEMM operands live here PRE-ROUNDED to tf32 (rna) so that mma.sync's
// tf32 truncation is exact (numerically identical to round-9's rna-at-STS).
// ---------------------------------------------------------------------------
__device__ float g_rq [(size_t)BATCH * QN * DIN];
__device__ float g_rk [(size_t)BATCH * KN * DIN];
__device__ float g_rv [(size_t)BATCH * KN * DIN];
__device__ float g_rwq[(size_t)DPROJ * DIN];
__device__ float g_rwk[(size_t)DPROJ * DIN];
__device__ float g_rwv[(size_t)DPROJ * DIN];
__device__ float g_pq [(size_t)BATCH * QN * DPROJ];   // rounded in epilogue
__device__ float g_pk [(size_t)BATCH * KN * DPROJ];   // rounded in epilogue
__device__ float g_pvT[(size_t)BATCH * DPROJ * KN];   // V proj transposed, rounded

// ---------------------------------------------------------------------------
__device__ __forceinline__ uint32_t f2tf32(float f) {
    uint32_t u;
    asm("cvt.rna.tf32.f32 %0, %1;" : "=r"(u) : "f"(f));
    return u;
}

__device__ __forceinline__ void mma_tf32(float* d, const uint32_t* a, const uint32_t* b) {
    asm volatile(
        "mma.sync.aligned.m16n8k8.row.col.f32.tf32.tf32.f32 "
        "{%0,%1,%2,%3}, {%4,%5,%6,%7}, {%8,%9}, {%0,%1,%2,%3};\n"
        : "+f"(d[0]), "+f"(d[1]), "+f"(d[2]), "+f"(d[3])
        : "r"(a[0]), "r"(a[1]), "r"(a[2]), "r"(a[3]),
          "r"(b[0]), "r"(b[1]));
}

__device__ __forceinline__ void ldsm4(uint32_t& r0, uint32_t& r1,
                                      uint32_t& r2, uint32_t& r3, uint32_t addr) {
    asm volatile("ldmatrix.sync.aligned.m8n8.x4.shared.b16 {%0,%1,%2,%3}, [%4];"
        : "=r"(r0), "=r"(r1), "=r"(r2), "=r"(r3) : "r"(addr));
}

__device__ __forceinline__ void cp16(uint32_t dst, const void* src) {
    asm volatile("cp.async.cg.shared.global [%0], [%1], 16;" :: "r"(dst), "l"(src) : "memory");
}

// ---------------------------------------------------------------------------
// NT tensor-core GEMM, tf32(pre-rounded)/fp32-acc:
//   C[m,n] = scale*sum_k A[m,k]*Bm[n,k] (+bias)
// BIAS: 0 none, 1 col bias[n], 2 row bias[m].  ROUND: rna-tf32 the output.
// Block 128x128, BK=16, 4 warps (2x2, 64x64 warp tile), 4-stage cp.async
// pipeline (no register staging), ldmatrix fragments, stride-20 padded smem.
// 128 thr/CTA, 80KB dynamic smem -> 2 CTAs/SM.
// ---------------------------------------------------------------------------
#define BK 16
#define STRD 20
#define STAGES 4
#define STAGE_WORDS (2 * 128 * STRD)              // A tile + B tile
#define STAGE_BYTES (STAGE_WORDS * 4)             // 20480
#define GSMEM_BYTES (STAGES * STAGE_BYTES)        // 81920

template <int BIAS, int ROUND>
__global__ __launch_bounds__(128) void gemm_tc(
    const float* __restrict__ A, const float* __restrict__ Bm,
    const float* __restrict__ bias, float* __restrict__ C,
    int N, int K, float scale,
    long aStride, long bStride, long cStride)
{
    extern __shared__ uint32_t smem[];
    const uint32_t sbase = (uint32_t)__cvta_generic_to_shared(smem);

    const int bm = blockIdx.y * 128;
    const int bn = blockIdx.x * 128;
    A  += blockIdx.z * aStride;
    Bm += blockIdx.z * bStride;
    C  += blockIdx.z * cStride;

    const int tid  = threadIdx.x;
    const int lane = tid & 31;
    const int wid  = tid >> 5;
    const int wm   = (wid & 1) * 64;
    const int wn   = (wid >> 1) * 64;
    const int lr   = lane >> 2;
    const int lc   = lane & 3;

    // cp.async coords: per warp-iter, 8 rows x 4 chunks of 16B.
    // row = lane&7 within group (conflict-free smem banks: r*20 pattern),
    // chunk = lane>>3 (lanes 0/8/16/24 same row -> gmem sectors merge).
    const int cp_r = lane & 7;
    const int cp_c = lane >> 3;

    // ldmatrix per-lane offsets (validated rounds 8-9)
    const int mi = lane >> 3;
    const int aRow = (lane & 7) + (mi & 1) * 8;
    const int aCol = (mi >> 1) * 4;
    const int bRow = (lane & 7) + (mi >> 1) * 8;
    const int bCol = (mi & 1) * 4;
    const uint32_t aLane = (uint32_t)((aRow * STRD + aCol) * 4);
    const uint32_t bLane = (uint32_t)((128 * STRD + bRow * STRD + bCol) * 4);

    float acc[4][8][4];
#pragma unroll
    for (int i = 0; i < 4; i++)
#pragma unroll
        for (int j = 0; j < 8; j++)
#pragma unroll
            for (int q = 0; q < 4; q++) acc[i][j][q] = 0.f;

    const int T = K / BK;

    auto cp_tile = [&](int t, int s) {
        const uint32_t stA = sbase + s * STAGE_BYTES;
        const uint32_t stB = stA + 128 * STRD * 4;
        const long k0 = (long)t * BK;
        const uint32_t soff = (uint32_t)((cp_r * STRD + cp_c * 4) * 4);
        const long goff = k0 + cp_c * 4;
#pragma unroll
        for (int i = 0; i < 4; i++) {
            const int row = (i * 4 + wid) * 8 + cp_r;
            cp16(stA + soff + (uint32_t)(i * 4 + wid) * (8 * STRD * 4),
                 A + (long)(bm + row) * K + goff);
            cp16(stB + soff + (uint32_t)(i * 4 + wid) * (8 * STRD * 4),
                 Bm + (long)(bn + row) * K + goff);
        }
        asm volatile("cp.async.commit_group;" ::: "memory");
    };

    auto compute = [&](int s) {
        const uint32_t asA = sbase + s * STAGE_BYTES + aLane;
        const uint32_t bsB = sbase + s * STAGE_BYTES + bLane;
#pragma unroll
        for (int kk = 0; kk < BK; kk += 8) {
            uint32_t af[4][4], bf[8][2];
#pragma unroll
            for (int fm = 0; fm < 4; fm++) {
                const int m = wm + fm * 16;
                ldsm4(af[fm][0], af[fm][1], af[fm][2], af[fm][3],
                      asA + (uint32_t)((m * STRD + kk) * 4));
            }
#pragma unroll
            for (int fp = 0; fp < 4; fp++) {
                const int n = wn + fp * 16;
                ldsm4(bf[2 * fp][0], bf[2 * fp][1], bf[2 * fp + 1][0], bf[2 * fp + 1][1],
                      bsB + (uint32_t)((n * STRD + kk) * 4));
            }
#pragma unroll
            for (int fm = 0; fm < 4; fm++)
#pragma unroll
                for (int fn = 0; fn < 8; fn++)
                    mma_tf32(acc[fm][fn], af[fm], bf[fn]);
        }
    };

    // Prologue: fill stages 0..2
    cp_tile(0, 0);
    cp_tile(1, 1);
    cp_tile(2, 2);

    for (int t = 0; t < T; t++) {
        const int s = t & (STAGES - 1);
        if (t + 2 < T)      asm volatile("cp.async.wait_group 2;" ::: "memory");
        else if (t + 1 < T) asm volatile("cp.async.wait_group 1;" ::: "memory");
        else                asm volatile("cp.async.wait_group 0;" ::: "memory");
        __syncthreads();   // tile t visible; all warps done with buffer (t-1)&3
        if (t + 3 < T) cp_tile(t + 3, (t + 3) & (STAGES - 1));
        compute(s);
    }

    // Epilogue
#pragma unroll
    for (int fm = 0; fm < 4; fm++) {
        const int r = bm + wm + fm * 16 + lr;
        float br0 = 0.f, br1 = 0.f;
        if (BIAS == 2) { br0 = bias[r]; br1 = bias[r + 8]; }
#pragma unroll
        for (int fn = 0; fn < 8; fn++) {
            const int c = bn + wn + fn * 8 + lc * 2;
            float bc0 = 0.f, bc1 = 0.f;
            if (BIAS == 1) { bc0 = bias[c]; bc1 = bias[c + 1]; }
            float2 v0, v1;
            v0.x = acc[fm][fn][0] * scale + bc0 + br0;
            v0.y = acc[fm][fn][1] * scale + bc1 + br0;
            v1.x = acc[fm][fn][2] * scale + bc0 + br1;
            v1.y = acc[fm][fn][3] * scale + bc1 + br1;
            if (ROUND) {
                v0.x = __uint_as_float(f2tf32(v0.x));
                v0.y = __uint_as_float(f2tf32(v0.y));
                v1.x = __uint_as_float(f2tf32(v1.x));
                v1.y = __uint_as_float(f2tf32(v1.y));
            }
            *(float2*)&C[(long)r * N + c] = v0;
            *(float2*)&C[(long)(r + 8) * N + c] = v1;
        }
    }
}

// ---------------------------------------------------------------------------
// Elementwise fp32 -> tf32(rna) pre-round
// ---------------------------------------------------------------------------
__global__ __launch_bounds__(256) void round_tf32_k(
    const float4* __restrict__ in, float4* __restrict__ out, long n4)
{
    long i = (long)blockIdx.x * blockDim.x + threadIdx.x;
    const long st = (long)gridDim.x * blockDim.x;
    for (; i < n4; i += st) {
        float4 v = in[i];
        float4 o;
        o.x = __uint_as_float(f2tf32(v.x));
        o.y = __uint_as_float(f2tf32(v.y));
        o.z = __uint_as_float(f2tf32(v.z));
        o.w = __uint_as_float(f2tf32(v.w));
        out[i] = o;
    }
}

// ---------------------------------------------------------------------------
// Row softmax with mask; output tf32-rounded (feeds ctx GEMM).
// Masked entries contribute nothing and output exact 0 (matches reference).
// ---------------------------------------------------------------------------
__global__ __launch_bounds__(256) void softmax_mask(
    float* __restrict__ S, const int* __restrict__ mask)
{
    const int row = blockIdx.x;
    const int b = row / QN;
    float* sp = S + (long)row * KN;
    const int* mp = mask + (long)b * KN;

    const int tid = threadIdx.x;
    __shared__ float red[32];

    float vals[8];
    int ms[8];
    float lmax = -INFINITY;
#pragma unroll
    for (int i = 0; i < 8; i++) {
        int k = tid + i * 256;
        vals[i] = sp[k];
        ms[i] = mp[k];
        if (ms[i]) lmax = fmaxf(lmax, vals[i]);
    }
#pragma unroll
    for (int o = 16; o > 0; o >>= 1)
        lmax = fmaxf(lmax, __shfl_xor_sync(0xffffffffu, lmax, o));
    if ((tid & 31) == 0) red[tid >> 5] = lmax;
    __syncthreads();
    float rmax = (tid < 8) ? red[tid] : -INFINITY;
#pragma unroll
    for (int o = 4; o > 0; o >>= 1)
        rmax = fmaxf(rmax, __shfl_xor_sync(0xffffffffu, rmax, o));
    if (tid == 0) red[0] = rmax;
    __syncthreads();
    rmax = red[0];

    float lsum = 0.f;
#pragma unroll
    for (int i = 0; i < 8; i++) {
        vals[i] = ms[i] ? __expf(vals[i] - rmax) : 0.f;
        lsum += vals[i];
    }
#pragma unroll
    for (int o = 16; o > 0; o >>= 1)
        lsum += __shfl_xor_sync(0xffffffffu, lsum, o);
    __syncthreads();
    if ((tid & 31) == 0) red[tid >> 5] = lsum;
    __syncthreads();
    float rsum = (tid < 8) ? red[tid] : 0.f;
#pragma unroll
    for (int o = 4; o > 0; o >>= 1)
        rsum += __shfl_xor_sync(0xffffffffu, rsum, o);
    if (tid == 0) red[0] = rsum;
    __syncthreads();
    rsum = red[0];

    float inv = (rsum > 0.f) ? (1.f / rsum) : 0.f;
#pragma unroll
    for (int i = 0; i < 8; i++) {
        int k = tid + i * 256;
        sp[k] = __uint_as_float(f2tf32(vals[i] * inv));
    }
}

// ---------------------------------------------------------------------------
// kernel_launch
// Inputs: query, key, value, mask, Wq, bq, Wk, bk, Wv, bv
// Output: [ctx (B*QN*DPROJ) | attn (B*QN*KN)]
// ---------------------------------------------------------------------------
extern "C" void kernel_launch(void* const* d_in, const int* in_sizes, int n_in,
                              void* d_out, int out_size)
{
    const float* query = (const float*)d_in[0];
    const float* key   = (const float*)d_in[1];
    const float* value = (const float*)d_in[2];
    const int*   mask  = (const int*)d_in[3];
    const float* Wq    = (const float*)d_in[4];
    const float* bq    = (const float*)d_in[5];
    const float* Wk    = (const float*)d_in[6];
    const float* bk    = (const float*)d_in[7];
    const float* Wv    = (const float*)d_in[8];
    const float* bv    = (const float*)d_in[9];

    float* ctx  = (float*)d_out;
    float* attn = (float*)d_out + (size_t)BATCH * QN * DPROJ;

    float *rq, *rk, *rv, *rwq, *rwk, *rwv, *pq, *pk, *pvT;
    cudaGetSymbolAddress((void**)&rq,  g_rq);
    cudaGetSymbolAddress((void**)&rk,  g_rk);
    cudaGetSymbolAddress((void**)&rv,  g_rv);
    cudaGetSymbolAddress((void**)&rwq, g_rwq);
    cudaGetSymbolAddress((void**)&rwk, g_rwk);
    cudaGetSymbolAddress((void**)&rwv, g_rwv);
    cudaGetSymbolAddress((void**)&pq,  g_pq);
    cudaGetSymbolAddress((void**)&pk,  g_pk);
    cudaGetSymbolAddress((void**)&pvT, g_pvT);

    cudaFuncSetAttribute(gemm_tc<0, 0>, cudaFuncAttributeMaxDynamicSharedMemorySize, GSMEM_BYTES);
    cudaFuncSetAttribute(gemm_tc<1, 1>, cudaFuncAttributeMaxDynamicSharedMemorySize, GSMEM_BYTES);
    cudaFuncSetAttribute(gemm_tc<2, 1>, cudaFuncAttributeMaxDynamicSharedMemorySize, GSMEM_BYTES);

    // 1) Pre-round all external GEMM inputs to tf32 (rna) once.
    {
        const long nBig = (long)BATCH * QN * DIN / 4;
        const long nW   = (long)DPROJ * DIN / 4;
        round_tf32_k<<<2048, 256>>>((const float4*)query, (float4*)rq, nBig);
        round_tf32_k<<<2048, 256>>>((const float4*)key,   (float4*)rk, nBig);
        round_tf32_k<<<2048, 256>>>((const float4*)value, (float4*)rv, nBig);
        round_tf32_k<<<512, 256>>>((const float4*)Wq, (float4*)rwq, nW);
        round_tf32_k<<<512, 256>>>((const float4*)Wk, (float4*)rwk, nW);
        round_tf32_k<<<512, 256>>>((const float4*)Wv, (float4*)rwv, nW);
    }

    dim3 blk(128);

    // 2) Q/K projections (batches fused): pq[tok,d] = rq @ rwq^T + bq (col-bias, rounded)
    {
        dim3 grid(DPROJ / 128, (BATCH * QN) / 128, 1);
        gemm_tc<1, 1><<<grid, blk, GSMEM_BYTES>>>(rq, rwq, bq, pq, DPROJ, DIN, 1.f, 0, 0, 0);
        gemm_tc<1, 1><<<grid, blk, GSMEM_BYTES>>>(rk, rwk, bk, pk, DPROJ, DIN, 1.f, 0, 0, 0);
    }

    // 3) V projection transposed: pvT[d,tok] = rwv @ rv^T + bv[d] (row-bias, rounded)
    {
        dim3 grid(KN / 128, DPROJ / 128, BATCH);
        gemm_tc<2, 1><<<grid, blk, GSMEM_BYTES>>>(rwv, rv, bv, pvT, KN, DIN, 1.f,
                                                  0, (long)KN * DIN, (long)DPROJ * KN);
    }

    // 4) Scores: attn_raw[q,k] = (pq . pk)/32 per batch (unrounded fp32 out)
    {
        dim3 grid(KN / 128, QN / 128, BATCH);
        gemm_tc<0, 0><<<grid, blk, GSMEM_BYTES>>>(pq, pk, nullptr, attn, KN, DPROJ,
                                                  0.03125f,
                                                  (long)QN * DPROJ, (long)KN * DPROJ,
                                                  (long)QN * KN);
    }

    // 5) Masked softmax in-place (output tf32-rounded)
    softmax_mask<<<BATCH * QN, 256>>>(attn, mask);

    // 6) ctx[q,d] = sum_k attn[q,k] * pvT[d,k]  (NT)
    {
        dim3 grid(DPROJ / 128, QN / 128, BATCH);
        gemm_tc<0, 0><<<grid, blk, GSMEM_BYTES>>>(attn, pvT, nullptr, ctx, DPROJ, KN,
                                                  1.f,
                                                  (long)QN * KN, (long)DPROJ * KN,
                                                  (long)QN * DPROJ);
    }
}

// round 16
// speedup vs baseline: 2.1110x; 1.3236x over previous
#include <cuda_runtime.h>
#include <math.h>
#include <stdint.h>

#define BATCH 8
#define QN 2048
#define KN 2048
#define DIN 1024
#define DPROJ 1024

// ---------------------------------------------------------------------------
// Scratch (__device__ globals; allocation-free).
// All GEMM operands live here PRE-ROUNDED to tf32 (rna) so that mma.sync's
// tf32 truncation is exact.
// ---------------------------------------------------------------------------
__device__ float g_rq [(size_t)BATCH * QN * DIN];
__device__ float g_rk [(size_t)BATCH * KN * DIN];
__device__ float g_rv [(size_t)BATCH * KN * DIN];
__device__ float g_rwq[(size_t)DPROJ * DIN];
__device__ float g_rwk[(size_t)DPROJ * DIN];
__device__ float g_rwv[(size_t)DPROJ * DIN];
__device__ float g_pq [(size_t)BATCH * QN * DPROJ];
__device__ float g_pk [(size_t)BATCH * KN * DPROJ];
__device__ float g_pvT[(size_t)BATCH * DPROJ * KN];

// ---------------------------------------------------------------------------
__device__ __forceinline__ uint32_t f2tf32(float f) {
    uint32_t u;
    asm("cvt.rna.tf32.f32 %0, %1;" : "=r"(u) : "f"(f));
    return u;
}

__device__ __forceinline__ void mma_tf32(float* d, const uint32_t* a, const uint32_t* b) {
    asm volatile(
        "mma.sync.aligned.m16n8k8.row.col.f32.tf32.tf32.f32 "
        "{%0,%1,%2,%3}, {%4,%5,%6,%7}, {%8,%9}, {%0,%1,%2,%3};\n"
        : "+f"(d[0]), "+f"(d[1]), "+f"(d[2]), "+f"(d[3])
        : "r"(a[0]), "r"(a[1]), "r"(a[2]), "r"(a[3]),
          "r"(b[0]), "r"(b[1]));
}

__device__ __forceinline__ void ldsm4(uint32_t& r0, uint32_t& r1,
                                      uint32_t& r2, uint32_t& r3, uint32_t addr) {
    asm volatile("ldmatrix.sync.aligned.m8n8.x4.shared.b16 {%0,%1,%2,%3}, [%4];"
        : "=r"(r0), "=r"(r1), "=r"(r2), "=r"(r3) : "r"(addr));
}

__device__ __forceinline__ void cp16(uint32_t dst, const void* src) {
    asm volatile("cp.async.cg.shared.global [%0], [%1], 16;" :: "r"(dst), "l"(src) : "memory");
}

// ---------------------------------------------------------------------------
// NT tensor-core GEMM, tf32(pre-rounded)/fp32-acc:
//   C[m,n] = scale*sum_k A[m,k]*Bm[n,k] (+bias)
// BIAS: 0 none, 1 col bias[n], 2 row bias[m].  ROUND: rna-tf32 the output.
// Block 128x128, BK=32, SW128-swizzled smem tiles (128B rows, quad = (k>>2)^(r&7))
// -> conflict-free cp.async stores AND ldmatrix reads. 4 warps (2x2, 64x64),
// 3-stage cp.async pipeline, one __syncthreads per k32. 96KB smem, 2 CTA/SM.
// ---------------------------------------------------------------------------
#define BK 32
#define STAGES 3
#define TILE_BYTES (128 * 128)                    // 128 rows x 128B
#define STAGE_BYTES (2 * TILE_BYTES)              // A + B = 32768
#define GSMEM_BYTES (STAGES * STAGE_BYTES)        // 98304

template <int BIAS, int ROUND>
__global__ __launch_bounds__(128) void gemm_tc(
    const float* __restrict__ A, const float* __restrict__ Bm,
    const float* __restrict__ bias, float* __restrict__ C,
    int N, int K, float scale,
    long aStride, long bStride, long cStride)
{
    extern __shared__ uint32_t smem[];
    const uint32_t sbase = (uint32_t)__cvta_generic_to_shared(smem);

    const int bm = blockIdx.y * 128;
    const int bn = blockIdx.x * 128;
    A  += blockIdx.z * aStride;
    Bm += blockIdx.z * bStride;
    C  += blockIdx.z * cStride;

    const int tid  = threadIdx.x;
    const int lane = tid & 31;
    const int wid  = tid >> 5;
    const int wm   = (wid & 1) * 64;
    const int wn   = (wid >> 1) * 64;
    const int lr   = lane >> 2;
    const int lc   = lane & 3;

    // ldmatrix lane geometry: mi = matrix id (lane>>3), rl = row in matrix.
    // For both A and B groups here, (row & 7) == rl, so the swizzle XOR is ^rl.
    const int mi  = lane >> 3;
    const int rl  = lane & 7;
    const int miL = mi & 1;
    const int miH = mi >> 1;
    // A matrices: m0:(r,kk) m1:(r+8,kk) m2:(r,kk+4) m3:(r+8,kk+4)
    const uint32_t rowAb = (uint32_t)(wm + rl + miL * 8) * 128;
    // B matrices: m0:(n+r,kk) m1:(n+r,kk+4) m2:(n+8+r,kk) m3:(n+8+r,kk+4)
    const uint32_t rowBb = (uint32_t)(wn + rl + miH * 8) * 128;

    // cp.async geometry: per iter, warp covers rows [wid*4 .. wid*4+3] (+16*i),
    // 8 lanes per row each storing 16B; quad = c ^ (row&7) -> conflict-free.
    const int cp_rb = wid * 4 + (lane >> 3);
    const int cp_c  = lane & 7;

    float acc[4][8][4];
#pragma unroll
    for (int i = 0; i < 4; i++)
#pragma unroll
        for (int j = 0; j < 8; j++)
#pragma unroll
            for (int q = 0; q < 4; q++) acc[i][j][q] = 0.f;

    const int T = K / BK;

    auto cp_tile = [&](int t, int s) {
        const uint32_t sA = sbase + s * STAGE_BYTES;
        const uint32_t sB = sA + TILE_BYTES;
        const long k0 = (long)t * BK + cp_c * 4;
#pragma unroll
        for (int i = 0; i < 8; i++) {
            const int row = i * 16 + cp_rb;
            const uint32_t soff = (uint32_t)row * 128 +
                                  (uint32_t)((cp_c ^ (row & 7)) << 4);
            cp16(sA + soff, A + (long)(bm + row) * K + k0);
            cp16(sB + soff, Bm + (long)(bn + row) * K + k0);
        }
        asm volatile("cp.async.commit_group;" ::: "memory");
    };

    auto compute = [&](int s) {
        const uint32_t sA = sbase + s * STAGE_BYTES + rowAb;
        const uint32_t sB = sbase + s * STAGE_BYTES + TILE_BYTES + rowBb;
#pragma unroll
        for (int k8 = 0; k8 < 4; k8++) {
            uint32_t af[4][4], bf[8][2];
            const uint32_t qa = (uint32_t)(((k8 * 2 + miH) ^ rl) << 4);
            const uint32_t qb = (uint32_t)(((k8 * 2 + miL) ^ rl) << 4);
#pragma unroll
            for (int fm = 0; fm < 4; fm++)
                ldsm4(af[fm][0], af[fm][1], af[fm][2], af[fm][3],
                      sA + fm * 2048 + qa);
#pragma unroll
            for (int fp = 0; fp < 4; fp++)
                ldsm4(bf[2 * fp][0], bf[2 * fp][1], bf[2 * fp + 1][0], bf[2 * fp + 1][1],
                      sB + fp * 2048 + qb);
#pragma unroll
            for (int fm = 0; fm < 4; fm++)
#pragma unroll
                for (int fn = 0; fn < 8; fn++)
                    mma_tf32(acc[fm][fn], af[fm], bf[fn]);
        }
    };

    // Prologue: stages 0,1
    cp_tile(0, 0);
    cp_tile(1, 1);

    int s = 0;
    for (int t = 0; t < T; t++) {
        if (t + 1 < T) asm volatile("cp.async.wait_group 1;" ::: "memory");
        else           asm volatile("cp.async.wait_group 0;" ::: "memory");
        __syncthreads();   // tile t visible everywhere; stage (t+2)%3 fully consumed
        if (t + 2 < T) {
            int sn = s + 2; if (sn >= STAGES) sn -= STAGES;
            cp_tile(t + 2, sn);
        }
        compute(s);
        if (++s == STAGES) s = 0;
    }

    // Epilogue (fragment layout validated rounds 7-9)
#pragma unroll
    for (int fm = 0; fm < 4; fm++) {
        const int r = bm + wm + fm * 16 + lr;
        float br0 = 0.f, br1 = 0.f;
        if (BIAS == 2) { br0 = bias[r]; br1 = bias[r + 8]; }
#pragma unroll
        for (int fn = 0; fn < 8; fn++) {
            const int c = bn + wn + fn * 8 + lc * 2;
            float bc0 = 0.f, bc1 = 0.f;
            if (BIAS == 1) { bc0 = bias[c]; bc1 = bias[c + 1]; }
            float2 v0, v1;
            v0.x = acc[fm][fn][0] * scale + bc0 + br0;
            v0.y = acc[fm][fn][1] * scale + bc1 + br0;
            v1.x = acc[fm][fn][2] * scale + bc0 + br1;
            v1.y = acc[fm][fn][3] * scale + bc1 + br1;
            if (ROUND) {
                v0.x = __uint_as_float(f2tf32(v0.x));
                v0.y = __uint_as_float(f2tf32(v0.y));
                v1.x = __uint_as_float(f2tf32(v1.x));
                v1.y = __uint_as_float(f2tf32(v1.y));
            }
            *(float2*)&C[(long)r * N + c] = v0;
            *(float2*)&C[(long)(r + 8) * N + c] = v1;
        }
    }
}

// ---------------------------------------------------------------------------
// Elementwise fp32 -> tf32(rna) pre-round
// ---------------------------------------------------------------------------
__global__ __launch_bounds__(256) void round_tf32_k(
    const float4* __restrict__ in, float4* __restrict__ out, long n4)
{
    long i = (long)blockIdx.x * blockDim.x + threadIdx.x;
    const long st = (long)gridDim.x * blockDim.x;
    for (; i < n4; i += st) {
        float4 v = in[i];
        float4 o;
        o.x = __uint_as_float(f2tf32(v.x));
        o.y = __uint_as_float(f2tf32(v.y));
        o.z = __uint_as_float(f2tf32(v.z));
        o.w = __uint_as_float(f2tf32(v.w));
        out[i] = o;
    }
}

// ---------------------------------------------------------------------------
// Row softmax with mask; output tf32-rounded (feeds ctx GEMM).
// Masked entries contribute nothing and output exact 0 (matches reference).
// ---------------------------------------------------------------------------
__global__ __launch_bounds__(256) void softmax_mask(
    float* __restrict__ S, const int* __restrict__ mask)
{
    const int row = blockIdx.x;
    const int b = row / QN;
    float* sp = S + (long)row * KN;
    const int* mp = mask + (long)b * KN;

    const int tid = threadIdx.x;
    __shared__ float red[32];

    float vals[8];
    int ms[8];
    float lmax = -INFINITY;
#pragma unroll
    for (int i = 0; i < 8; i++) {
        int k = tid + i * 256;
        vals[i] = sp[k];
        ms[i] = mp[k];
        if (ms[i]) lmax = fmaxf(lmax, vals[i]);
    }
#pragma unroll
    for (int o = 16; o > 0; o >>= 1)
        lmax = fmaxf(lmax, __shfl_xor_sync(0xffffffffu, lmax, o));
    if ((tid & 31) == 0) red[tid >> 5] = lmax;
    __syncthreads();
    float rmax = (tid < 8) ? red[tid] : -INFINITY;
#pragma unroll
    for (int o = 4; o > 0; o >>= 1)
        rmax = fmaxf(rmax, __shfl_xor_sync(0xffffffffu, rmax, o));
    if (tid == 0) red[0] = rmax;
    __syncthreads();
    rmax = red[0];

    float lsum = 0.f;
#pragma unroll
    for (int i = 0; i < 8; i++) {
        vals[i] = ms[i] ? __expf(vals[i] - rmax) : 0.f;
        lsum += vals[i];
    }
#pragma unroll
    for (int o = 16; o > 0; o >>= 1)
        lsum += __shfl_xor_sync(0xffffffffu, lsum, o);
    __syncthreads();
    if ((tid & 31) == 0) red[tid >> 5] = lsum;
    __syncthreads();
    float rsum = (tid < 8) ? red[tid] : 0.f;
#pragma unroll
    for (int o = 4; o > 0; o >>= 1)
        rsum += __shfl_xor_sync(0xffffffffu, rsum, o);
    if (tid == 0) red[0] = rsum;
    __syncthreads();
    rsum = red[0];

    float inv = (rsum > 0.f) ? (1.f / rsum) : 0.f;
#pragma unroll
    for (int i = 0; i < 8; i++) {
        int k = tid + i * 256;
        sp[k] = __uint_as_float(f2tf32(vals[i] * inv));
    }
}

// ---------------------------------------------------------------------------
// kernel_launch
// Inputs: query, key, value, mask, Wq, bq, Wk, bk, Wv, bv
// Output: [ctx (B*QN*DPROJ) | attn (B*QN*KN)]
// ---------------------------------------------------------------------------
extern "C" void kernel_launch(void* const* d_in, const int* in_sizes, int n_in,
                              void* d_out, int out_size)
{
    const float* query = (const float*)d_in[0];
    const float* key   = (const float*)d_in[1];
    const float* value = (const float*)d_in[2];
    const int*   mask  = (const int*)d_in[3];
    const float* Wq    = (const float*)d_in[4];
    const float* bq    = (const float*)d_in[5];
    const float* Wk    = (const float*)d_in[6];
    const float* bk    = (const float*)d_in[7];
    const float* Wv    = (const float*)d_in[8];
    const float* bv    = (const float*)d_in[9];

    float* ctx  = (float*)d_out;
    float* attn = (float*)d_out + (size_t)BATCH * QN * DPROJ;

    float *rq, *rk, *rv, *rwq, *rwk, *rwv, *pq, *pk, *pvT;
    cudaGetSymbolAddress((void**)&rq,  g_rq);
    cudaGetSymbolAddress((void**)&rk,  g_rk);
    cudaGetSymbolAddress((void**)&rv,  g_rv);
    cudaGetSymbolAddress((void**)&rwq, g_rwq);
    cudaGetSymbolAddress((void**)&rwk, g_rwk);
    cudaGetSymbolAddress((void**)&rwv, g_rwv);
    cudaGetSymbolAddress((void**)&pq,  g_pq);
    cudaGetSymbolAddress((void**)&pk,  g_pk);
    cudaGetSymbolAddress((void**)&pvT, g_pvT);

    cudaFuncSetAttribute(gemm_tc<0, 0>, cudaFuncAttributeMaxDynamicSharedMemorySize, GSMEM_BYTES);
    cudaFuncSetAttribute(gemm_tc<1, 1>, cudaFuncAttributeMaxDynamicSharedMemorySize, GSMEM_BYTES);
    cudaFuncSetAttribute(gemm_tc<2, 1>, cudaFuncAttributeMaxDynamicSharedMemorySize, GSMEM_BYTES);

    // 1) Pre-round all external GEMM inputs to tf32 (rna) once.
    {
        const long nBig = (long)BATCH * QN * DIN / 4;
        const long nW   = (long)DPROJ * DIN / 4;
        round_tf32_k<<<2048, 256>>>((const float4*)query, (float4*)rq, nBig);
        round_tf32_k<<<2048, 256>>>((const float4*)key,   (float4*)rk, nBig);
        round_tf32_k<<<2048, 256>>>((const float4*)value, (float4*)rv, nBig);
        round_tf32_k<<<512, 256>>>((const float4*)Wq, (float4*)rwq, nW);
        round_tf32_k<<<512, 256>>>((const float4*)Wk, (float4*)rwk, nW);
        round_tf32_k<<<512, 256>>>((const float4*)Wv, (float4*)rwv, nW);
    }

    dim3 blk(128);

    // 2) Q/K projections (batches fused): pq[tok,d] = rq @ rwq^T + bq (col-bias, rounded)
    {
        dim3 grid(DPROJ / 128, (BATCH * QN) / 128, 1);
        gemm_tc<1, 1><<<grid, blk, GSMEM_BYTES>>>(rq, rwq, bq, pq, DPROJ, DIN, 1.f, 0, 0, 0);
        gemm_tc<1, 1><<<grid, blk, GSMEM_BYTES>>>(rk, rwk, bk, pk, DPROJ, DIN, 1.f, 0, 0, 0);
    }

    // 3) V projection transposed: pvT[d,tok] = rwv @ rv^T + bv[d] (row-bias, rounded)
    {
        dim3 grid(KN / 128, DPROJ / 128, BATCH);
        gemm_tc<2, 1><<<grid, blk, GSMEM_BYTES>>>(rwv, rv, bv, pvT, KN, DIN, 1.f,
                                                  0, (long)KN * DIN, (long)DPROJ * KN);
    }

    // 4) Scores: attn_raw[q,k] = (pq . pk)/32 per batch (unrounded fp32 out)
    {
        dim3 grid(KN / 128, QN / 128, BATCH);
        gemm_tc<0, 0><<<grid, blk, GSMEM_BYTES>>>(pq, pk, nullptr, attn, KN, DPROJ,
                                                  0.03125f,
                                                  (long)QN * DPROJ, (long)KN * DPROJ,
                                                  (long)QN * KN);
    }

    // 5) Masked softmax in-place (output tf32-rounded)
    softmax_mask<<<BATCH * QN, 256>>>(attn, mask);

    // 6) ctx[q,d] = sum_k attn[q,k] * pvT[d,k]  (NT)
    {
        dim3 grid(DPROJ / 128, QN / 128, BATCH);
        gemm_tc<0, 0><<<grid, blk, GSMEM_BYTES>>>(attn, pvT, nullptr, ctx, DPROJ, KN,
                                                  1.f,
                                                  (long)QN * KN, (long)DPROJ * KN,
                                                  (long)QN * DPROJ);
    }
}